// round 14
// baseline (speedup 1.0000x reference)
#include <cuda_runtime.h>
#include <cstdint>

#define BB 4
#define SS 512
#define DD 128
#define HH 8
#define SCP 514    // scores pitch (even -> 8B-aligned LDS.64 rows)

// scratch (static device memory; no runtime allocation)
__device__ float g_q[BB*SS*DD];
__device__ float g_k[BB*SS*DD];
__device__ float g_v[BB*SS*DD];
__device__ float g_attn[BB*SS*DD];

// ---------------- f32x2 helpers ----------------
__device__ __forceinline__ unsigned long long pack2(float x) {
    unsigned long long r;
    asm("mov.b64 %0, {%1, %1};" : "=l"(r) : "f"(x));
    return r;
}
__device__ __forceinline__ unsigned long long pack2v(float lo, float hi) {
    unsigned long long r;
    asm("mov.b64 %0, {%1, %2};" : "=l"(r) : "f"(lo), "f"(hi));
    return r;
}
__device__ __forceinline__ void fma2(unsigned long long& d, unsigned long long a, unsigned long long b) {
    asm("fma.rn.f32x2 %0, %1, %2, %0;" : "+l"(d) : "l"(a), "l"(b));
}
__device__ __forceinline__ void unpack2(unsigned long long v, float& lo, float& hi) {
    asm("mov.b64 {%0, %1}, %2;" : "=f"(lo), "=f"(hi) : "l"(v));
}
__device__ __forceinline__ unsigned int smem_u32(const void* p) {
    return (unsigned int)__cvta_generic_to_shared(p);
}

// ---------------------------------------------------------------------------
// Kernel A: QKV projection with smem-staged weights. grid=(128,3), block=256
// ---------------------------------------------------------------------------
__global__ __launch_bounds__(256) void qkv_kernel(
    const float* __restrict__ x,
    const float* __restrict__ wq, const float* __restrict__ bq,
    const float* __restrict__ wk, const float* __restrict__ bk,
    const float* __restrict__ wv, const float* __restrict__ bv)
{
    extern __shared__ float sm[];
    float* ws = sm;                 // [128][128]
    float (*xs)[128] = (float(*)[128])(sm + 128 * 128);   // [16][128]

    const int t = threadIdx.x;
    const int mat = blockIdx.y;
    const int row0 = blockIdx.x * 16;

    const float* W    = (mat == 0) ? wq : (mat == 1) ? wk : wv;
    const float* bias = (mat == 0) ? bq : (mat == 1) ? bk : bv;
    float* out        = (mat == 0) ? g_q : (mat == 1) ? g_k : g_v;

    #pragma unroll
    for (int i = t; i < 4096; i += 256)
        ((float4*)ws)[i] = ((const float4*)W)[i];
    #pragma unroll
    for (int i = t; i < 512; i += 256)
        ((float4*)xs)[i] = ((const float4*)(x + (size_t)row0 * DD))[i];
    __syncthreads();

    const int c4 = t & 31;
    const int rg = t >> 5;
    const ulonglong2* W2 = (const ulonglong2*)ws;

    unsigned long long acc[2][2];
    acc[0][0] = acc[0][1] = acc[1][0] = acc[1][1] = 0ull;

    #pragma unroll 8
    for (int d = 0; d < 128; d++) {
        ulonglong2 w = W2[d * 32 + c4];
        #pragma unroll
        for (int r = 0; r < 2; r++) {
            unsigned long long xr = pack2(xs[rg * 2 + r][d]);
            fma2(acc[r][0], xr, w.x);
            fma2(acc[r][1], xr, w.y);
        }
    }
    float4 bb = ((const float4*)bias)[c4];
    #pragma unroll
    for (int r = 0; r < 2; r++) {
        float4 o;
        unpack2(acc[r][0], o.x, o.y);
        unpack2(acc[r][1], o.z, o.w);
        o.x += bb.x; o.y += bb.y; o.z += bb.z; o.w += bb.w;
        ((float4*)(out + (size_t)(row0 + rg * 2 + r) * DD))[c4] = o;
    }
}

// ---------------------------------------------------------------------------
// Kernel B: FUSED st_bias + attention.
// grid = 512 (b = bx>>7, q0 = (bx&127)*4), block = 256 (8 warps), 2 CTAs/SM.
// Phase 0: bias -> scores directly. Warp w owns q=w>>1, k in [(w&1)*256,+256):
//   8 groups x 32 rows; slab = 32 rows x 16 d (pitch 20), cp.async 2-deep,
//   lane owns 1 row, weights = smem u64 broadcasts, ZERO shuffles.
// Phase 1: qk/4 ADDED into scores (64-row K chunks, conflict-free LDS).
// Phase 2: softmax (+mask).  Phase 3: PV (warp = head).
// smem = 115072 B
// ---------------------------------------------------------------------------
#define BUFB 2560   // bytes per bias staging buffer (32 rows x 80 B)
__global__ __launch_bounds__(256, 2) void attn_fused_kernel(
    const float* __restrict__ st, const int* __restrict__ mask,
    const float* __restrict__ wst)
{
    extern __shared__ float smem[];
    float* scores = smem;                        // [32][SCP]   (row = q*8+h)
    float* stage  = smem + 32 * SCP;             // 10240 fl (bias slabs / K chunks)
    float* qs     = stage + 10240;               // [4][128]
    float* mask_s = qs + 512;                    // [512]
    float* rinv_s = mask_s + 512;                // [32]
    unsigned long long* wp = (unsigned long long*)(rinv_s + 32);   // [64 dp][8 h]
    float* outp = (float*)wp;                    // [8 h][4 q][16 e], reused after bias

    const int tid  = threadIdx.x;
    const int lane = tid & 31;
    const int wid  = tid >> 5;
    const int b    = blockIdx.x >> 7;
    const int q0   = (blockIdx.x & 127) * 4;

    // ---- init: weight table, q tile, mask ----
    #pragma unroll
    for (int idx = tid; idx < 512; idx += 256) {
        int j = idx >> 3, h = idx & 7;
        wp[idx] = pack2v(wst[(2 * j) * HH + h], wst[(2 * j + 1) * HH + h]);
    }
    if (tid < 128) {
        int r = tid >> 5, c4 = tid & 31;
        ((float4*)(qs + r * 128))[c4] =
            ((const float4*)(g_q + (size_t)(b * SS + q0 + r) * DD))[c4];
    }
    #pragma unroll
    for (int i = tid; i < 512; i += 256)
        mask_s[i] = mask[b * SS + i] ? -10000.0f : 0.0f;
    __syncthreads();

    // ---------------- Phase 0: bias -> scores ----------------
    {
        const int q     = wid >> 1;
        const int kbase = (wid & 1) * 256;
        float* stg = stage + wid * (2 * BUFB / 4);
        const unsigned stgu = smem_u32(stg);
        const int prow = lane >> 2;    // staging row-subgroup
        const int pchk = lane & 3;     // 16B chunk
        const size_t Rq = ((size_t)(b * SS + q0 + q)) * SS + kbase;

        // prefetch slab (group g_, d-window s_) into buffer b_
        #define BPREF(g_, s_, b_) do {                                              \
            const char* gsrc = (const char*)st + (Rq + (g_) * 32 + prow) * 512      \
                               + (s_) * 64 + pchk * 16;                             \
            unsigned sdst = stgu + (b_) * BUFB + prow * 80 + pchk * 16;             \
            _Pragma("unroll")                                                       \
            for (int ii = 0; ii < 4; ii++)                                          \
                asm volatile("cp.async.cg.shared.global [%0], [%1], 16;"            \
                             :: "r"(sdst + ii * 8 * 80), "l"(gsrc + (size_t)ii * 8 * 512) \
                             : "memory");                                           \
            asm volatile("cp.async.commit_group;");                                 \
        } while (0)

        int buf = 0;
        BPREF(0, 0, 0);
        unsigned long long acc[8];

        for (int t2 = 0; t2 < 64; t2++) {
            const int g = t2 >> 3, s = t2 & 7;
            const int tn = (t2 + 1 < 64) ? t2 + 1 : t2;   // dummy tail prefetch
            BPREF(tn >> 3, tn & 7, buf ^ 1);

            asm volatile("cp.async.wait_group 1;" ::: "memory");
            __syncwarp();

            if (s == 0) {
                #pragma unroll
                for (int h = 0; h < 8; h++) acc[h] = 0ull;
            }

            const float* srow = stg + buf * (BUFB / 4) + lane * 20;  // 16 d window
            const unsigned long long* wsl = wp + (s * 8) * 8;        // 8 dp x 8 h
            const ulonglong2* e2 = (const ulonglong2*)srow;          // lane*5 mod 8 distinct
            #pragma unroll
            for (int pp = 0; pp < 4; pp++) {
                ulonglong2 e = e2[pp];
                const unsigned long long* wA = wsl + (2 * pp) * 8;
                const unsigned long long* wB = wsl + (2 * pp + 1) * 8;
                #pragma unroll
                for (int h = 0; h < 8; h++) {
                    fma2(acc[h], e.x, wA[h]);
                    fma2(acc[h], e.y, wB[h]);
                }
            }
            __syncwarp();    // all lanes done reading buf before it is refilled

            if (s == 7) {
                const int k = kbase + g * 32 + lane;
                #pragma unroll
                for (int h = 0; h < 8; h++) {
                    float lo, hi;
                    unpack2(acc[h], lo, hi);
                    scores[(q * 8 + h) * SCP + k] = lo + hi;
                }
            }
            buf ^= 1;
        }
        #undef BPREF
    }
    __syncthreads();

    // ---------------- Phase 1: scores += qk/4 ----------------
    {
        const int qq = tid >> 6;          // 0..3
        const int kl = tid & 63;
        const ulonglong2* qr = (const ulonglong2*)(qs + qq * 128);

        for (int c = 0; c < 8; c++) {
            // stage 64 K rows (pitch 33 float4) into stage region
            const float4* kg = (const float4*)(g_k + (size_t)(b * SS + c * 64) * DD);
            #pragma unroll
            for (int idx = tid; idx < 2048; idx += 256)
                ((float4*)stage)[(idx >> 5) * 33 + (idx & 31)] = kg[idx];
            __syncthreads();

            unsigned long long acc2[8];
            #pragma unroll
            for (int h = 0; h < 8; h++) acc2[h] = 0ull;
            const ulonglong2* kr = (const ulonglong2*)(stage + kl * 132);
            #pragma unroll
            for (int j = 0; j < 32; j++) {
                ulonglong2 kk2 = kr[j];     // conflict-free
                ulonglong2 a   = qr[j];     // warp-broadcast (qq uniform per warp)
                fma2(acc2[j >> 2], a.x, kk2.x);
                fma2(acc2[j >> 2], a.y, kk2.y);
            }
            const int kidx = c * 64 + kl;
            float* sd = scores + (qq * 8) * SCP + kidx;
            #pragma unroll
            for (int h = 0; h < 8; h++) {
                float lo, hi;
                unpack2(acc2[h], lo, hi);
                sd[h * SCP] = fmaf(lo + hi, 0.25f, sd[h * SCP]);
            }
            __syncthreads();
        }
    }

    // ---------------- Phase 2: softmax per (q,h) row ----------------
    for (int rr = wid; rr < 32; rr += 8) {
        float* srow = scores + rr * SCP;
        float vals[16];
        float mx = -1e30f;
        #pragma unroll
        for (int j = 0; j < 16; j++) {
            int k = lane + 32 * j;
            float v = srow[k] + mask_s[k];
            vals[j] = v;
            mx = fmaxf(mx, v);
        }
        #pragma unroll
        for (int o = 16; o > 0; o >>= 1) mx = fmaxf(mx, __shfl_xor_sync(0xffffffffu, mx, o));
        float sum = 0.f;
        #pragma unroll
        for (int j = 0; j < 16; j++) {
            float e = __expf(vals[j] - mx);
            srow[lane + 32 * j] = e;
            sum += e;
        }
        #pragma unroll
        for (int o = 16; o > 0; o >>= 1) sum += __shfl_xor_sync(0xffffffffu, sum, o);
        if (lane == 0) rinv_s[rr] = 1.0f / sum;
    }
    __syncthreads();

    // ---------------- Phase 3: PV (warp = head; f32x2 over k-pairs) ----------
    {
        const int h  = wid;
        const int e  = lane & 15;
        const int kk = lane >> 4;     // 0/1
        const float* vbase = g_v + (size_t)(b * SS) * DD + h * 16 + e;

        unsigned long long acc2[4];
        #pragma unroll
        for (int q = 0; q < 4; q++) acc2[q] = 0ull;

        #pragma unroll 4
        for (int i = 0; i < 64; i++) {
            const int k4 = kk * 4 + i * 8;
            float v0 = vbase[(size_t)(k4 + 0) * DD];
            float v1 = vbase[(size_t)(k4 + 1) * DD];
            float v2 = vbase[(size_t)(k4 + 2) * DD];
            float v3 = vbase[(size_t)(k4 + 3) * DD];
            unsigned long long vp01 = pack2v(v0, v1);
            unsigned long long vp23 = pack2v(v2, v3);
            #pragma unroll
            for (int q = 0; q < 4; q++) {
                const float* p = scores + (q * 8 + h) * SCP + k4;   // 8B-aligned
                unsigned long long pa = *(const unsigned long long*)p;
                unsigned long long pb = *(const unsigned long long*)(p + 2);
                fma2(acc2[q], pa, vp01);
                fma2(acc2[q], pb, vp23);
            }
        }
        __syncthreads();   // wp region free before outp writes (and scores reads done block-wide? per-warp only; safe: outp!=scores)
        #pragma unroll
        for (int q = 0; q < 4; q++) {
            float lo, hi;
            unpack2(acc2[q], lo, hi);
            float s = lo + hi;
            s += __shfl_xor_sync(0xffffffffu, s, 16);
            if (lane < 16)
                outp[(h * 4 + q) * 16 + e] = s;
        }
    }
    __syncthreads();

    #pragma unroll
    for (int id = tid; id < 512; id += 256) {
        int e = id & 15, h = (id >> 4) & 7, q = id >> 7;
        g_attn[(size_t)(b * SS + q0 + q) * DD + h * 16 + e] =
            outp[(h * 4 + q) * 16 + e] * rinv_s[q * 8 + h];
    }
}

// ---------------------------------------------------------------------------
// Kernel C: out = LN(residual + attn @ wo + bo), smem-staged wo.
// grid=128 (16 rows), block=256
// ---------------------------------------------------------------------------
__global__ __launch_bounds__(256) void out_ln_kernel(
    const float* __restrict__ x, const float* __restrict__ wo,
    const float* __restrict__ bo, const float* __restrict__ g,
    const float* __restrict__ bbeta, float* __restrict__ out)
{
    extern __shared__ float sm[];
    float* ws = sm;                                         // [128][128]
    float (*as_)[128] = (float(*)[128])(sm + 128 * 128);    // [16][128]
    float (*ys)[128]  = (float(*)[128])(sm + 128 * 128 + 16 * 128); // [16][128]

    const int row0 = blockIdx.x * 16;
    const int t = threadIdx.x;

    #pragma unroll
    for (int i = t; i < 4096; i += 256)
        ((float4*)ws)[i] = ((const float4*)wo)[i];
    #pragma unroll
    for (int i = t; i < 512; i += 256)
        ((float4*)as_)[i] = ((const float4*)(g_attn + (size_t)row0 * DD))[i];
    __syncthreads();

    const int c4 = t & 31;
    const int rg = t >> 5;   // rows rg*2, rg*2+1
    const ulonglong2* W2 = (const ulonglong2*)ws;

    unsigned long long acc[2][2];
    acc[0][0] = acc[0][1] = acc[1][0] = acc[1][1] = 0ull;

    #pragma unroll 8
    for (int d = 0; d < 128; d++) {
        ulonglong2 w = W2[d * 32 + c4];
        #pragma unroll
        for (int r = 0; r < 2; r++) {
            unsigned long long xr = pack2(as_[rg * 2 + r][d]);
            fma2(acc[r][0], xr, w.x);
            fma2(acc[r][1], xr, w.y);
        }
    }
    float4 bb = ((const float4*)bo)[c4];
    #pragma unroll
    for (int r = 0; r < 2; r++) {
        float4 o;
        unpack2(acc[r][0], o.x, o.y);
        unpack2(acc[r][1], o.z, o.w);
        float4 xr = ((const float4*)(x + (size_t)(row0 + rg * 2 + r) * DD))[c4];
        o.x += bb.x + xr.x; o.y += bb.y + xr.y;
        o.z += bb.z + xr.z; o.w += bb.w + xr.w;
        ((float4*)ys[rg * 2 + r])[c4] = o;
    }
    __syncthreads();

    // LayerNorm: 8 warps x 2 rows
    const int wid = t >> 5, lane = t & 31;
    #pragma unroll
    for (int r = 0; r < 2; r++) {
        const int row = wid * 2 + r;
        float4 v = ((float4*)ys[row])[lane];
        float s = v.x + v.y + v.z + v.w;
        #pragma unroll
        for (int o = 16; o > 0; o >>= 1) s += __shfl_xor_sync(0xffffffffu, s, o);
        float mu = s * (1.f / 128.f);
        float dx = v.x - mu, dy = v.y - mu, dz = v.z - mu, dw = v.w - mu;
        float ss = dx * dx + dy * dy + dz * dz + dw * dw;
        #pragma unroll
        for (int o = 16; o > 0; o >>= 1) ss += __shfl_xor_sync(0xffffffffu, ss, o);
        float rstd = rsqrtf(ss * (1.f / 128.f) + 1e-5f);
        float4 gg = ((const float4*)g)[lane];
        float4 bb2 = ((const float4*)bbeta)[lane];
        float4 o4;
        o4.x = dx * rstd * gg.x + bb2.x;
        o4.y = dy * rstd * gg.y + bb2.y;
        o4.z = dz * rstd * gg.z + bb2.z;
        o4.w = dw * rstd * gg.w + bb2.w;
        ((float4*)(out + (size_t)(row0 + row) * DD))[lane] = o4;
    }
}

// ---------------------------------------------------------------------------
extern "C" void kernel_launch(void* const* d_in, const int* in_sizes, int n_in,
                              void* d_out, int out_size)
{
    const float* x    = (const float*)d_in[0];
    const float* st   = (const float*)d_in[1];
    const int*   mask = (const int*)  d_in[2];
    const float* wq   = (const float*)d_in[3];
    const float* bq   = (const float*)d_in[4];
    const float* wk   = (const float*)d_in[5];
    const float* bk   = (const float*)d_in[6];
    const float* wv   = (const float*)d_in[7];
    const float* bv   = (const float*)d_in[8];
    const float* wo   = (const float*)d_in[9];
    const float* bo   = (const float*)d_in[10];
    const float* wst  = (const float*)d_in[11];
    const float* lng  = (const float*)d_in[12];
    const float* lnb  = (const float*)d_in[13];
    float* out = (float*)d_out;

    const int SMEM_QKV  = (128 * 128 + 16 * 128) * 4;                           // 73728 B
    const int SMEM_ATTN = (32 * SCP + 10240 + 512 + 512 + 32 + 1024) * 4;       // 115072 B
    const int SMEM_OLN  = (128 * 128 + 16 * 128 + 16 * 128) * 4;                // 81920 B
    cudaFuncSetAttribute(qkv_kernel,  cudaFuncAttributeMaxDynamicSharedMemorySize, SMEM_QKV);
    cudaFuncSetAttribute(attn_fused_kernel, cudaFuncAttributeMaxDynamicSharedMemorySize, SMEM_ATTN);
    cudaFuncSetAttribute(out_ln_kernel, cudaFuncAttributeMaxDynamicSharedMemorySize, SMEM_OLN);

    qkv_kernel<<<dim3(128, 3), 256, SMEM_QKV>>>(x, wq, bq, wk, bk, wv, bv);
    attn_fused_kernel<<<512, 256, SMEM_ATTN>>>(st, mask, wst);
    out_ln_kernel<<<128, 256, SMEM_OLN>>>(x, wo, bo, lng, lnb, out);
}

// round 15
// speedup vs baseline: 1.1540x; 1.1540x over previous
#include <cuda_runtime.h>
#include <cstdint>

#define BB 4
#define SS 512
#define DD 128
#define HH 8
#define SC_PITCH 516

// scratch (static device memory; no runtime allocation)
__device__ float g_q[BB*SS*DD];
__device__ float g_k[BB*SS*DD];
__device__ float g_v[BB*SS*DD];

// ---------------- f32x2 helpers ----------------
__device__ __forceinline__ unsigned long long pack2(float x) {
    unsigned long long r;
    asm("mov.b64 %0, {%1, %1};" : "=l"(r) : "f"(x));
    return r;
}
__device__ __forceinline__ unsigned long long pack2v(float lo, float hi) {
    unsigned long long r;
    asm("mov.b64 %0, {%1, %2};" : "=l"(r) : "f"(lo), "f"(hi));
    return r;
}
__device__ __forceinline__ void fma2(unsigned long long& d, unsigned long long a, unsigned long long b) {
    asm("fma.rn.f32x2 %0, %1, %2, %0;" : "+l"(d) : "l"(a), "l"(b));
}
__device__ __forceinline__ void unpack2(unsigned long long v, float& lo, float& hi) {
    asm("mov.b64 {%0, %1}, %2;" : "=f"(lo), "=f"(hi) : "l"(v));
}
__device__ __forceinline__ unsigned int smem_u32(const void* p) {
    return (unsigned int)__cvta_generic_to_shared(p);
}

__device__ float g_bias[(size_t)BB*SS*SS*HH];   // [b*S+q][k][h], h innermost

// ---------------------------------------------------------------------------
// Kernel A: FUSED st_bias stream + QKV projection (warp-specialized).
// grid = 148, block = 384 (12 warps), 1 CTA/SM.
//   warps 0-7 : R10 bias stream (4 rows/lane d-slabs, 2-deep cp.async).
//   warps 8-11: qkv worker — tiles of 16 rows, weights via L2 LDG, hidden
//               in the stream's idle issue slots. Named barrier 1 (128 thr).
// smem = 4KB wp + 160KB stage + 8.3KB xq = 176192 B
// ---------------------------------------------------------------------------
#define BIAS_GRID 148
#define SLAB_PITCH 20                 // floats per slab row (16 d + 4 pad)
#define SLAB_F (128 * SLAB_PITCH)     // 2560 floats = 10240 B per buffer
#define N_TASKS 8192                  // 1,048,576 rows / 128
__global__ __launch_bounds__(384) void bias_qkv_kernel(
    const float* __restrict__ st, const float* __restrict__ wst,
    const float* __restrict__ x,
    const float* __restrict__ wq, const float* __restrict__ bq,
    const float* __restrict__ wk, const float* __restrict__ bk,
    const float* __restrict__ wv, const float* __restrict__ bv)
{
    extern __shared__ float sm[];
    unsigned long long* wp = (unsigned long long*)sm;   // [64 d-pairs][8 heads] u64
    float* stage = sm + 1024;                            // 8 warps x 2 bufs x SLAB_F
    float* xq    = sm + 1024 + 8 * 2 * SLAB_F;           // [16][129] qkv x tile

    const int tid  = threadIdx.x;
    const int lane = tid & 31;
    const int wid  = tid >> 5;

    // weight table: wp[j*8+h] = (wst[2j][h], wst[2j+1][h])
    for (int idx = tid; idx < 512; idx += 384) {
        int j = idx >> 3, h = idx & 7;
        wp[idx] = pack2v(wst[(2 * j) * HH + h], wst[(2 * j + 1) * HH + h]);
    }
    __syncthreads();

    if (tid < 256) {
        // ================= bias stream (warps 0-7), exact R10 =================
        float* buf0 = stage + wid * (2 * SLAB_F);
        const unsigned bufu = smem_u32(buf0);

        const int prow = lane >> 2;
        const int pchk = lane & 3;

        #define PREF(row0_, s_, b_) do {                                                 \
            const char* gsrc = (const char*)st + ((size_t)(row0_) + prow) * 512          \
                               + (s_) * 64 + pchk * 16;                                  \
            unsigned sdst = bufu + (b_) * (SLAB_F * 4) + prow * 80 + pchk * 16;          \
            _Pragma("unroll")                                                            \
            for (int i = 0; i < 16; i++)                                                 \
                asm volatile("cp.async.cg.shared.global [%0], [%1], 16;"                 \
                             :: "r"(sdst + i * 8 * 80), "l"(gsrc + (size_t)i * 8 * 512)  \
                             : "memory");                                                \
            asm volatile("cp.async.commit_group;");                                      \
        } while (0)

        const unsigned NW = BIAS_GRID * 8;   // 1184 warps
        unsigned task = blockIdx.x * 8 + wid;

        PREF((size_t)task * 128, 0, 0);
        int buf = 0;

        for (; task < N_TASKS; task += NW) {
            const size_t row0 = (size_t)task * 128;
            unsigned long long acc[4][8];
            #pragma unroll
            for (int r = 0; r < 4; r++)
                #pragma unroll
                for (int h = 0; h < 8; h++) acc[r][h] = 0ull;

            for (int s = 0; s < 8; s++) {
                if (s < 7) {
                    PREF(row0, s + 1, buf ^ 1);
                } else {
                    const unsigned nt = task + NW;
                    const size_t nr0 = (nt < N_TASKS) ? (size_t)nt * 128 : row0;
                    PREF(nr0, 0, buf ^ 1);
                }
                asm volatile("cp.async.wait_group 1;" ::: "memory");
                __syncwarp();

                const float* slab = stage + wid * (2 * SLAB_F) + buf * SLAB_F;
                const unsigned long long* wslab = wp + s * 64;

                #pragma unroll
                for (int q = 0; q < 4; q++) {
                    ulonglong2 e[4];
                    #pragma unroll
                    for (int r = 0; r < 4; r++)
                        e[r] = *(const ulonglong2*)(slab + (lane + 32 * r) * SLAB_PITCH + q * 4);
                    const unsigned long long* w0 = wslab + (2 * q) * 8;
                    #pragma unroll
                    for (int h = 0; h < 8; h++) {
                        const unsigned long long wv2 = w0[h];
                        fma2(acc[0][h], e[0].x, wv2);
                        fma2(acc[1][h], e[1].x, wv2);
                        fma2(acc[2][h], e[2].x, wv2);
                        fma2(acc[3][h], e[3].x, wv2);
                    }
                    const unsigned long long* w1 = wslab + (2 * q + 1) * 8;
                    #pragma unroll
                    for (int h = 0; h < 8; h++) {
                        const unsigned long long wv2 = w1[h];
                        fma2(acc[0][h], e[0].y, wv2);
                        fma2(acc[1][h], e[1].y, wv2);
                        fma2(acc[2][h], e[2].y, wv2);
                        fma2(acc[3][h], e[3].y, wv2);
                    }
                }
                __syncwarp();
                buf ^= 1;
            }

            #pragma unroll
            for (int r = 0; r < 4; r++) {
                float o[8];
                #pragma unroll
                for (int h = 0; h < 8; h++) {
                    float lo, hi;
                    unpack2(acc[r][h], lo, hi);
                    o[h] = lo + hi;
                }
                float* dst = g_bias + (row0 + lane + 32 * r) * HH;
                *(float4*)dst       = make_float4(o[0], o[1], o[2], o[3]);
                *(float4*)(dst + 4) = make_float4(o[4], o[5], o[6], o[7]);
            }
        }
        #undef PREF
    } else {
        // ================= qkv worker (warps 8-11, 128 threads) ================
        const int t = tid - 256;
        for (int tt = blockIdx.x; tt < 384; tt += BIAS_GRID) {
            const int mat  = tt / 128;           // 0=q 1=k 2=v
            const int row0 = (tt % 128) * 16;
            const float* W    = (mat == 0) ? wq : (mat == 1) ? wk : wv;
            const float* bias = (mat == 0) ? bq : (mat == 1) ? bk : bv;
            float* out        = (mat == 0) ? g_q : (mat == 1) ? g_k : g_v;

            // stage x tile (16 rows, pitch 129)
            #pragma unroll
            for (int i = t; i < 2048; i += 128)
                xq[(i >> 7) * 129 + (i & 127)] = x[(size_t)row0 * DD + i];
            asm volatile("bar.sync 1, 128;" ::: "memory");

            const int c4 = t & 31;
            const int rg = t >> 5;               // rows rg*4 .. rg*4+3
            const ulonglong2* W2 = (const ulonglong2*)W;

            unsigned long long acc[4][2];
            #pragma unroll
            for (int r = 0; r < 4; r++) { acc[r][0] = 0ull; acc[r][1] = 0ull; }

            #pragma unroll 4
            for (int d = 0; d < 128; d++) {
                ulonglong2 w = __ldg(&W2[d * 32 + c4]);   // L2-resident
                #pragma unroll
                for (int r = 0; r < 4; r++) {
                    unsigned long long xr = pack2(xq[(rg * 4 + r) * 129 + d]);
                    fma2(acc[r][0], xr, w.x);
                    fma2(acc[r][1], xr, w.y);
                }
            }
            float4 bb = __ldg(&((const float4*)bias)[c4]);
            #pragma unroll
            for (int r = 0; r < 4; r++) {
                float4 o;
                unpack2(acc[r][0], o.x, o.y);
                unpack2(acc[r][1], o.z, o.w);
                o.x += bb.x; o.y += bb.y; o.z += bb.z; o.w += bb.w;
                ((float4*)(out + (size_t)(row0 + rg * 4 + r) * DD))[c4] = o;
            }
            asm volatile("bar.sync 1, 128;" ::: "memory");   // before next staging
        }
    }
}

// ---------------------------------------------------------------------------
// Kernel B: attention (qk + bias + mask + softmax + PV) + out-proj + LayerNorm.
// grid = 256 (b = bx>>6, q0 = (bx&63)*8), block = 512.
// Phases 1-3 = R13. Epilogue: reuse scores region for wo, GEMM + residual +
// LN in-block, write d_out directly.
// ---------------------------------------------------------------------------
__global__ __launch_bounds__(512, 1) void attn_kernel(
    const int* __restrict__ mask, const float* __restrict__ x,
    const float* __restrict__ wo, const float* __restrict__ bo,
    const float* __restrict__ lng, const float* __restrict__ lnb,
    float* __restrict__ out)
{
    extern __shared__ float smem[];
    float* scores = smem;                               // [64][SC_PITCH]; later wo[128][128]
    float* qs     = scores + 64 * SC_PITCH;             // [8][128]
    float* mask_s = qs + 8 * 128;                       // [512]
    float* rinv_s = mask_s + 512;                       // [64] (q*8+h)
    float* ks     = rinv_s + 64;                        // [128][132] K chunks
    float* outp   = ks;                                 // [2][8][8][16] = 2048 fl
    float* att_s  = ks + 2048;                          // [8][132]
    float* ys     = ks + 3104;                          // [8][132]

    const int tid  = threadIdx.x;
    const int lane = tid & 31;
    const int wid  = tid >> 5;
    const int b    = blockIdx.x >> 6;
    const int q0   = (blockIdx.x & 63) * 8;

    if (tid < 256)
        ((float4*)qs)[tid] = ((const float4*)(g_q + (size_t)(b * SS + q0) * DD))[tid];
    mask_s[tid] = mask[b * SS + tid] ? -10000.0f : 0.0f;
    __syncthreads();

    // ---------------- Phase 1: scores = qk/4 + bias (2 q per thread) --------
    {
        const int g  = tid >> 8;          // 0/1: 64-row half of the chunk
        const int q2 = (tid >> 6) & 3;    // q pair index
        const int kl = tid & 63;

        for (int c = 0; c < 4; c++) {
            const float4* kg = (const float4*)(g_k + (size_t)(b * SS + c * 128) * DD);
            #pragma unroll
            for (int idx = tid; idx < 128 * 32; idx += 512)
                ((float4*)ks)[(idx >> 5) * 33 + (idx & 31)] = kg[idx];
            __syncthreads();

            unsigned long long acc2[2][8];
            #pragma unroll
            for (int r = 0; r < 2; r++)
                #pragma unroll
                for (int h = 0; h < 8; h++) acc2[r][h] = 0ull;

            const ulonglong2* kr  = (const ulonglong2*)(ks + (g * 64 + kl) * 132);
            const ulonglong2* qr0 = (const ulonglong2*)(qs + (q2 * 2) * 128);
            const ulonglong2* qr1 = (const ulonglong2*)(qs + (q2 * 2 + 1) * 128);
            #pragma unroll
            for (int j = 0; j < 32; j++) {
                ulonglong2 kk2 = kr[j];        // conflict-free (stride 132)
                ulonglong2 a0  = qr0[j];       // warp-broadcast
                ulonglong2 a1  = qr1[j];       // warp-broadcast
                fma2(acc2[0][j >> 2], a0.x, kk2.x);
                fma2(acc2[0][j >> 2], a0.y, kk2.y);
                fma2(acc2[1][j >> 2], a1.x, kk2.x);
                fma2(acc2[1][j >> 2], a1.y, kk2.y);
            }

            const int kidx = c * 128 + g * 64 + kl;
            #pragma unroll
            for (int r = 0; r < 2; r++) {
                const int q = q2 * 2 + r;
                const float4* brow = (const float4*)(g_bias +
                    ((size_t)(b * SS + q0 + q) * SS + kidx) * HH);
                float4 b0 = __ldg(brow);
                float4 b1 = __ldg(brow + 1);
                float bh[8] = {b0.x, b0.y, b0.z, b0.w, b1.x, b1.y, b1.z, b1.w};

                float* sdst = scores + (q * 8) * SC_PITCH + kidx;
                #pragma unroll
                for (int h = 0; h < 8; h++) {
                    float lo, hi;
                    unpack2(acc2[r][h], lo, hi);
                    sdst[h * SC_PITCH] = fmaf(lo + hi, 0.25f, bh[h]);
                }
            }
            __syncthreads();
        }
    }

    // ---------------- Phase 2: softmax per (q,h) row ----------------
    for (int rr = wid; rr < 64; rr += 16) {
        float* srow = scores + rr * SC_PITCH;
        float vals[16];
        float mx = -1e30f;
        #pragma unroll
        for (int j = 0; j < 16; j++) {
            int k = lane + 32 * j;
            float v = srow[k] + mask_s[k];
            vals[j] = v;
            mx = fmaxf(mx, v);
        }
        #pragma unroll
        for (int o = 16; o > 0; o >>= 1) mx = fmaxf(mx, __shfl_xor_sync(0xffffffffu, mx, o));
        float sum = 0.f;
        #pragma unroll
        for (int j = 0; j < 16; j++) {
            float e = __expf(vals[j] - mx);
            srow[lane + 32 * j] = e;
            sum += e;
        }
        #pragma unroll
        for (int o = 16; o > 0; o >>= 1) sum += __shfl_xor_sync(0xffffffffu, sum, o);
        if (lane == 0) rinv_s[rr] = 1.0f / sum;
    }
    __syncthreads();

    // ---------------- Phase 3: PV (f32x2 over k-pairs, probs via LDS.128) ----
    {
        const int h   = wid & 7;
        const int ks2 = wid >> 3;      // k-half
        const int e   = lane & 15;
        const int kk  = lane >> 4;     // 0/1
        const float* vbase = g_v + (size_t)(b * SS) * DD + h * 16 + e;
        const float* sbase = scores + h * SC_PITCH;

        unsigned long long acc2[8];
        #pragma unroll
        for (int q = 0; q < 8; q++) acc2[q] = 0ull;

        const int kstart = ks2 * 256 + kk * 4;
        #pragma unroll 4
        for (int i = 0; i < 32; i++) {
            const int k4 = kstart + i * 8;
            float v0 = vbase[(size_t)(k4 + 0) * DD];
            float v1 = vbase[(size_t)(k4 + 1) * DD];
            float v2 = vbase[(size_t)(k4 + 2) * DD];
            float v3 = vbase[(size_t)(k4 + 3) * DD];
            unsigned long long vp01 = pack2v(v0, v1);
            unsigned long long vp23 = pack2v(v2, v3);
            #pragma unroll
            for (int q = 0; q < 8; q++) {
                ulonglong2 p2 = *(const ulonglong2*)(sbase + q * 8 * SC_PITCH + k4);
                fma2(acc2[q], p2.x, vp01);
                fma2(acc2[q], p2.y, vp23);
            }
        }
        #pragma unroll
        for (int q = 0; q < 8; q++) {
            float lo, hi;
            unpack2(acc2[q], lo, hi);
            float s = lo + hi;
            s += __shfl_xor_sync(0xffffffffu, s, 16);
            if (lane < 16)
                outp[((ks2 * 8 + h) * 8 + q) * 16 + e] = s;
        }
    }
    __syncthreads();

    // ---------------- Epilogue A: combine PV halves -> att_s; stage wo -------
    #pragma unroll
    for (int id = tid; id < 1024; id += 512) {
        int e = id & 15, q = (id >> 4) & 7, h = id >> 7;
        att_s[q * 132 + h * 16 + e] =
            (outp[((0 * 8 + h) * 8 + q) * 16 + e] +
             outp[((1 * 8 + h) * 8 + q) * 16 + e]) * rinv_s[q * 8 + h];
    }
    // wo into the (now free) scores region: flat [128][128]
    #pragma unroll
    for (int i = tid; i < 4096; i += 512)
        ((float4*)scores)[i] = ((const float4*)wo)[i];
    __syncthreads();

    // ---------------- Epilogue B: y = att @ wo + bo + x ----------------------
    {
        const int row = tid >> 6;      // 0..7
        const int cp  = tid & 63;      // column pair
        const float* arow = att_s + row * 132;
        const unsigned long long* wsl = (const unsigned long long*)scores + cp;

        unsigned long long acc = 0ull;
        #pragma unroll 8
        for (int d = 0; d < 128; d++)
            fma2(acc, pack2(arow[d]), wsl[d * 64]);

        float lo, hi;
        unpack2(acc, lo, hi);
        float2 bo2 = *(const float2*)(bo + cp * 2);
        float2 x2  = *(const float2*)(x + (size_t)(b * SS + q0 + row) * DD + cp * 2);
        ys[row * 132 + cp * 2]     = lo + bo2.x + x2.x;
        ys[row * 132 + cp * 2 + 1] = hi + bo2.y + x2.y;
    }
    __syncthreads();

    // ---------------- Epilogue C: LayerNorm (warps 0-7, 1 row each) ----------
    if (wid < 8) {
        float4 v = ((float4*)(ys + wid * 132))[lane];
        float s = v.x + v.y + v.z + v.w;
        #pragma unroll
        for (int o = 16; o > 0; o >>= 1) s += __shfl_xor_sync(0xffffffffu, s, o);
        float mu = s * (1.f / 128.f);
        float dx = v.x - mu, dy = v.y - mu, dz = v.z - mu, dw = v.w - mu;
        float ss = dx * dx + dy * dy + dz * dz + dw * dw;
        #pragma unroll
        for (int o = 16; o > 0; o >>= 1) ss += __shfl_xor_sync(0xffffffffu, ss, o);
        float rstd = rsqrtf(ss * (1.f / 128.f) + 1e-5f);
        float4 gg  = ((const float4*)lng)[lane];
        float4 bb2 = ((const float4*)lnb)[lane];
        float4 o4;
        o4.x = dx * rstd * gg.x + bb2.x;
        o4.y = dy * rstd * gg.y + bb2.y;
        o4.z = dz * rstd * gg.z + bb2.z;
        o4.w = dw * rstd * gg.w + bb2.w;
        ((float4*)(out + (size_t)(b * SS + q0 + wid) * DD))[lane] = o4;
    }
}

// ---------------------------------------------------------------------------
extern "C" void kernel_launch(void* const* d_in, const int* in_sizes, int n_in,
                              void* d_out, int out_size)
{
    const float* x    = (const float*)d_in[0];
    const float* st   = (const float*)d_in[1];
    const int*   mask = (const int*)  d_in[2];
    const float* wq   = (const float*)d_in[3];
    const float* bq   = (const float*)d_in[4];
    const float* wk   = (const float*)d_in[5];
    const float* bk   = (const float*)d_in[6];
    const float* wv   = (const float*)d_in[7];
    const float* bv   = (const float*)d_in[8];
    const float* wo   = (const float*)d_in[9];
    const float* bo   = (const float*)d_in[10];
    const float* wst  = (const float*)d_in[11];
    const float* lng  = (const float*)d_in[12];
    const float* lnb  = (const float*)d_in[13];
    float* out = (float*)d_out;

    const int SMEM_BQ   = (1024 + 8 * 2 * SLAB_F + 16 * 129) * 4;               // 176192 B
    const int SMEM_ATTN = (64 * SC_PITCH + 8 * 128 + 512 + 64 + 128 * 132) * 4; // 206080 B
    cudaFuncSetAttribute(bias_qkv_kernel, cudaFuncAttributeMaxDynamicSharedMemorySize, SMEM_BQ);
    cudaFuncSetAttribute(attn_kernel, cudaFuncAttributeMaxDynamicSharedMemorySize, SMEM_ATTN);

    bias_qkv_kernel<<<BIAS_GRID, 384, SMEM_BQ>>>(st, wst, x, wq, bq, wk, bk, wv, bv);
    attn_kernel<<<256, 512, SMEM_ATTN>>>(mask, x, wo, bo, lng, lnb, out);
}